// round 1
// baseline (speedup 1.0000x reference)
#include <cuda_runtime.h>
#include <cstdint>

// SNN forward: x[B,5] -> L1(32) -> spike -> L2(32) -> spike -> L3(16) -> spike -> L4(10) -> spike
// spike(v) = (v >= 1) with v = pre/2  <=>  pre >= 2.0f  (exact: /2 is lossless in fp32)
//
// Layer1 computed dense (160 FMA). Layers 2-4 exploit binary-spike sparsity:
// pre_j = sum over set bits i of W[j][i]  (column gather over ~0.7 expected bits).

#define B_THREADS 256

__global__ __launch_bounds__(B_THREADS)
void snn_kernel(const float* __restrict__ x,
                const float* __restrict__ W1,   // [32,5]
                const float* __restrict__ W2,   // [32,32]
                const float* __restrict__ W3,   // [16,32]
                const float* __restrict__ W4,   // [10,16]
                float* __restrict__ out)        // [B,10]
{
    __shared__ float sW1[32 * 5];
    __shared__ float sW2[32 * 32];
    __shared__ float sW3[16 * 32];
    __shared__ float sW4[10 * 16];
    __shared__ float sX[B_THREADS * 5];
    __shared__ float sOut[B_THREADS * 10];

    const int tid = threadIdx.x;

    // --- cooperative loads: weights + coalesced float4 x tile ---
    for (int i = tid; i < 32 * 5; i += B_THREADS)  sW1[i] = W1[i];
    for (int i = tid; i < 32 * 32; i += B_THREADS) sW2[i] = W2[i];
    for (int i = tid; i < 16 * 32; i += B_THREADS) sW3[i] = W3[i];
    for (int i = tid; i < 10 * 16; i += B_THREADS) sW4[i] = W4[i];

    {
        const float4* xv = reinterpret_cast<const float4*>(x) +
                           (size_t)blockIdx.x * (B_THREADS * 5 / 4);
        float4* sxv = reinterpret_cast<float4*>(sX);
        #pragma unroll
        for (int i = tid; i < B_THREADS * 5 / 4; i += B_THREADS)
            sxv[i] = xv[i];
    }
    __syncthreads();

    // --- per-thread row ---
    float xr[5];
    #pragma unroll
    for (int i = 0; i < 5; i++) xr[i] = sX[tid * 5 + i];

    // Layer 1: dense 32x5, build spike bitmask
    unsigned mask1 = 0;
    #pragma unroll
    for (int o = 0; o < 32; o++) {
        float a = sW1[o * 5 + 0] * xr[0];
        a = fmaf(sW1[o * 5 + 1], xr[1], a);
        a = fmaf(sW1[o * 5 + 2], xr[2], a);
        a = fmaf(sW1[o * 5 + 3], xr[3], a);
        a = fmaf(sW1[o * 5 + 4], xr[4], a);
        if (a >= 2.0f) mask1 |= (1u << o);
    }

    unsigned mask3 = 0;
    float acc4[10];
    #pragma unroll
    for (int j = 0; j < 10; j++) acc4[j] = 0.0f;
    bool have_out = false;

    if (mask1) {
        // Layer 2: sparse column gather (32 outputs)
        float acc2[32];
        #pragma unroll
        for (int j = 0; j < 32; j++) acc2[j] = 0.0f;
        unsigned m = mask1;
        while (m) {
            int i = __ffs(m) - 1;
            m &= m - 1;
            #pragma unroll
            for (int j = 0; j < 32; j++) acc2[j] += sW2[j * 32 + i];
        }
        unsigned mask2 = 0;
        #pragma unroll
        for (int j = 0; j < 32; j++)
            if (acc2[j] >= 2.0f) mask2 |= (1u << j);

        if (mask2) {
            // Layer 3: sparse column gather (16 outputs)
            float acc3[16];
            #pragma unroll
            for (int j = 0; j < 16; j++) acc3[j] = 0.0f;
            unsigned m3 = mask2;
            while (m3) {
                int i = __ffs(m3) - 1;
                m3 &= m3 - 1;
                #pragma unroll
                for (int j = 0; j < 16; j++) acc3[j] += sW3[j * 32 + i];
            }
            #pragma unroll
            for (int j = 0; j < 16; j++)
                if (acc3[j] >= 2.0f) mask3 |= (1u << j);

            if (mask3) {
                // Layer 4: sparse column gather (10 outputs)
                unsigned m4 = mask3;
                while (m4) {
                    int i = __ffs(m4) - 1;
                    m4 &= m4 - 1;
                    #pragma unroll
                    for (int j = 0; j < 10; j++) acc4[j] += sW4[j * 16 + i];
                }
                have_out = true;
            }
        }
    }

    // final spikes -> staged output
    #pragma unroll
    for (int j = 0; j < 10; j++) {
        float v = (have_out && acc4[j] >= 2.0f) ? 1.0f : 0.0f;
        sOut[tid * 10 + j] = v;
    }
    __syncthreads();

    // coalesced float4 store of the block's [256,10] tile
    {
        float4* ov = reinterpret_cast<float4*>(out) +
                     (size_t)blockIdx.x * (B_THREADS * 10 / 4);
        const float4* sov = reinterpret_cast<const float4*>(sOut);
        #pragma unroll
        for (int i = tid; i < B_THREADS * 10 / 4; i += B_THREADS)
            ov[i] = sov[i];
    }
}

extern "C" void kernel_launch(void* const* d_in, const int* in_sizes, int n_in,
                              void* d_out, int out_size)
{
    const float* x  = (const float*)d_in[0];
    const float* W1 = (const float*)d_in[1];
    const float* W2 = (const float*)d_in[2];
    const float* W3 = (const float*)d_in[3];
    const float* W4 = (const float*)d_in[4];
    float* out = (float*)d_out;

    const int B = in_sizes[0] / 5;          // 2097152
    const int grid = B / B_THREADS;         // 8192 (B divisible by 256)

    snn_kernel<<<grid, B_THREADS>>>(x, W1, W2, W3, W4, out);
}

// round 2
// speedup vs baseline: 1.1765x; 1.1765x over previous
#include <cuda_runtime.h>
#include <cstdint>

// SNN forward: x[B,5] -> L1(32) -> spike(pre>=2) -> L2(32) -> L3(16) -> L4(10)
// Key facts: spikes are binary; layer-2 preactivation acc2_j = sum_{i in mask1} W2[j][i]
// is bounded above by sum_{i in mask1} colmax[i], colmax[i] = max_j W2[j][i].
// If that bound < 2, layers 2-4 produce all zeros -> skip (common case ~96% of warps).

__device__ float g_colmax[32];

__global__ void colmax_kernel(const float* __restrict__ W2) {
    int i = threadIdx.x;
    if (i < 32) {
        float mx = W2[i];
        #pragma unroll
        for (int j = 1; j < 32; j++) mx = fmaxf(mx, W2[j * 32 + i]);
        g_colmax[i] = mx;
    }
}

#define B_THREADS 256

__global__ __launch_bounds__(B_THREADS)
void snn_kernel(const float* __restrict__ x,
                const float* __restrict__ W1,   // [32,5]
                const float* __restrict__ W2,   // [32,32]
                const float* __restrict__ W3,   // [16,32]
                const float* __restrict__ W4,   // [10,16]
                float* __restrict__ out)        // [B,10]
{
    __shared__ float sW1[160];               // 40 float4
    __shared__ float sColMax[32];
    __shared__ float sX[B_THREADS * 5];      // 320 float4
    __shared__ unsigned sMask[B_THREADS];    // 10-bit output mask per row

    const int tid = threadIdx.x;

    // --- per-block staging: W1 (vectorized), colmax, x tile ---
    if (tid < 40)
        reinterpret_cast<float4*>(sW1)[tid] = reinterpret_cast<const float4*>(W1)[tid];
    if (tid >= 64 && tid < 96)
        sColMax[tid - 64] = g_colmax[tid - 64];
    {
        const float4* xv = reinterpret_cast<const float4*>(x) + (size_t)blockIdx.x * 320;
        float4* sxv = reinterpret_cast<float4*>(sX);
        #pragma unroll
        for (int i = tid; i < 320; i += B_THREADS) sxv[i] = xv[i];
    }
    __syncthreads();

    const float x0 = sX[tid * 5 + 0];
    const float x1 = sX[tid * 5 + 1];
    const float x2 = sX[tid * 5 + 2];
    const float x3 = sX[tid * 5 + 3];
    const float x4 = sX[tid * 5 + 4];

    // --- Layer 1: dense 32x5, W1 delivered via LDS.128 broadcasts ---
    unsigned mask1 = 0;
    const float4* w4 = reinterpret_cast<const float4*>(sW1);
    #pragma unroll
    for (int c = 0; c < 8; c++) {          // 4 output rows per chunk
        float w[20];
        #pragma unroll
        for (int q = 0; q < 5; q++) {
            float4 t = w4[c * 5 + q];
            w[q * 4 + 0] = t.x; w[q * 4 + 1] = t.y;
            w[q * 4 + 2] = t.z; w[q * 4 + 3] = t.w;
        }
        #pragma unroll
        for (int r = 0; r < 4; r++) {
            float a = w[r * 5 + 0] * x0;
            a = fmaf(w[r * 5 + 1], x1, a);
            a = fmaf(w[r * 5 + 2], x2, a);
            a = fmaf(w[r * 5 + 3], x3, a);
            a = fmaf(w[r * 5 + 4], x4, a);
            if (a >= 2.0f) mask1 |= 1u << (c * 4 + r);
        }
    }

    // --- Layers 2-4: bound-check, rare exact path reads weights from L2 ---
    unsigned omask = 0;
    if (mask1) {
        float bound = 0.0f;
        unsigned m = mask1;
        while (m) {
            int i = __ffs(m) - 1;
            m &= m - 1;
            bound += sColMax[i];
        }
        if (bound >= 1.995f) {   // conservative: skip only when provably < 2
            // Layer 2 exact: acc2_j = sum_{i in mask1} W2[j][i]
            unsigned mask2 = 0;
            #pragma unroll
            for (int jc = 0; jc < 32; jc += 8) {
                float acc[8];
                #pragma unroll
                for (int j = 0; j < 8; j++) acc[j] = 0.0f;
                unsigned mm = mask1;
                while (mm) {
                    int i = __ffs(mm) - 1;
                    mm &= mm - 1;
                    #pragma unroll
                    for (int j = 0; j < 8; j++) acc[j] += W2[(jc + j) * 32 + i];
                }
                #pragma unroll
                for (int j = 0; j < 8; j++)
                    if (acc[j] >= 2.0f) mask2 |= 1u << (jc + j);
            }
            if (mask2) {
                unsigned mask3 = 0;
                #pragma unroll
                for (int jc = 0; jc < 16; jc += 8) {
                    float acc[8];
                    #pragma unroll
                    for (int j = 0; j < 8; j++) acc[j] = 0.0f;
                    unsigned mm = mask2;
                    while (mm) {
                        int i = __ffs(mm) - 1;
                        mm &= mm - 1;
                        #pragma unroll
                        for (int j = 0; j < 8; j++) acc[j] += W3[(jc + j) * 32 + i];
                    }
                    #pragma unroll
                    for (int j = 0; j < 8; j++)
                        if (acc[j] >= 2.0f) mask3 |= 1u << (jc + j);
                }
                if (mask3) {
                    float acc4[10];
                    #pragma unroll
                    for (int j = 0; j < 10; j++) acc4[j] = 0.0f;
                    unsigned mm = mask3;
                    while (mm) {
                        int i = __ffs(mm) - 1;
                        mm &= mm - 1;
                        #pragma unroll
                        for (int j = 0; j < 10; j++) acc4[j] += W4[j * 16 + i];
                    }
                    #pragma unroll
                    for (int j = 0; j < 10; j++)
                        if (acc4[j] >= 2.0f) omask |= 1u << j;
                }
            }
        }
    }

    sMask[tid] = omask;
    __syncthreads();

    // --- coalesced float4 output from bit masks: 640 float4 per block ---
    float4* ov = reinterpret_cast<float4*>(out) + (size_t)blockIdx.x * 640;
    #pragma unroll
    for (int f = tid; f < 640; f += B_THREADS) {
        int e0 = 4 * f;
        int r = e0 / 10;
        int c = e0 - r * 10;                 // c in {0,2,4,6,8}
        unsigned m0 = sMask[r];
        unsigned m1 = sMask[(r + 1) & (B_THREADS - 1)];  // only used when valid
        float4 o;
        o.x = ((m0 >> c) & 1u) ? 1.0f : 0.0f;
        int c1 = c + 1, c2 = c + 2, c3 = c + 3;
        o.y = (((c1 < 10 ? (m0 >> c1) : (m1 >> (c1 - 10))) & 1u)) ? 1.0f : 0.0f;
        o.z = (((c2 < 10 ? (m0 >> c2) : (m1 >> (c2 - 10))) & 1u)) ? 1.0f : 0.0f;
        o.w = (((c3 < 10 ? (m0 >> c3) : (m1 >> (c3 - 10))) & 1u)) ? 1.0f : 0.0f;
        ov[f] = o;
    }
}

extern "C" void kernel_launch(void* const* d_in, const int* in_sizes, int n_in,
                              void* d_out, int out_size)
{
    const float* x  = (const float*)d_in[0];
    const float* W1 = (const float*)d_in[1];
    const float* W2 = (const float*)d_in[2];
    const float* W3 = (const float*)d_in[3];
    const float* W4 = (const float*)d_in[4];
    float* out = (float*)d_out;

    const int B = in_sizes[0] / 5;          // 2097152
    const int grid = B / B_THREADS;         // 8192

    colmax_kernel<<<1, 32>>>(W2);
    snn_kernel<<<grid, B_THREADS>>>(x, W1, W2, W3, W4, out);
}